// round 16
// baseline (speedup 1.0000x reference)
#include <cuda_runtime.h>
#include <math.h>
#include <stdint.h>

#define NB    32
#define TT    512
#define NIN   50
#define HH    512
#define OUTF  66
#define MAXP  10
#define NJS   32
#define NBG   4
#define GB    8
#define NTHR  512
#define NCTA  128
#define PAD   516

__device__ float    g_hstep[2][NBG][HH][GB];     // parity h2 exchange, [j][b]
__device__ float    g_haltp[2][NBG][NJS][32];    // halt partials: [js][b*4+w]
__device__ unsigned g_flag[NBG][NJS][32];        // ONE monotone flag per CTA, 128B apart
__device__ float    g_yacc[NB * TT * OUTF];
__device__ unsigned g_slot[NBG][NJS][32];
__device__ unsigned g_exitcnt[NBG * 32];

__device__ __forceinline__ float sigm(float v) { return 1.0f / (1.0f + __expf(-v)); }
__device__ __forceinline__ void ffma2(unsigned long long& d, unsigned long long a,
                                      unsigned long long b) {
    asm("fma.rn.f32x2 %0, %1, %2, %0;" : "+l"(d) : "l"(a), "l"(b));
}
__device__ __forceinline__ float2 unpk(unsigned long long v) {
    float2 r; asm("mov.b64 {%0, %1}, %2;" : "=f"(r.x), "=f"(r.y) : "l"(v)); return r;
}
__device__ __forceinline__ unsigned ld_acq(const unsigned* p) {
    unsigned v;
    asm volatile("ld.acquire.gpu.global.u32 %0, [%1];" : "=r"(v) : "l"(p) : "memory");
    return v;
}
__device__ __forceinline__ void st_rel(unsigned* p, unsigned v) {
    asm volatile("st.release.gpu.global.u32 [%0], %1;" :: "l"(p), "r"(v) : "memory");
}

#define WHH_OFF    0
#define WIH_OFF    (64 * PAD)
#define WOUT_OFF   (WIH_OFF + 64 * 52)
#define WHALT_OFF  (WOUT_OFF + 66 * 16)
#define H_OFF      (WHALT_OFF + 16)              // [2][8][PAD] double-buffered
#define GX_OFF     (H_OFF + 2 * 8 * PAD)
#define DSM_FLOATS (GX_OFF + 512)                // 46192 floats = 184768 B

extern __shared__ float dsm[];

__global__ void __launch_bounds__(NTHR, 1)
act_lstm_main(const float* __restrict__ x,   const float* __restrict__ Wih,
              const float* __restrict__ Whh, const float* __restrict__ bias,
              const float* __restrict__ Wout,const float* __restrict__ bout,
              const float* __restrict__ Whalt,const float* __restrict__ bhaltp,
              float* __restrict__ out)
{
    const int bg = blockIdx.x >> 5, js = blockIdx.x & 31, bgbase = bg * GB;
    const int tid = threadIdx.x, lane = tid & 31, w = tid >> 5;
    const int rowl = tid >> 3, bl8 = tid & 7;
    const int grow = (rowl >> 4) * HH + js * 16 + (rowl & 15);
    const int b_own = lane & 7, jgrp = lane >> 3;
    const float bhalt = bhaltp[0];
    float* pout = out + (size_t)NB * TT * OUTF;

    float* whh_s = dsm + WHH_OFF;  float* wih_s   = dsm + WIH_OFF;
    float* wout_s = dsm + WOUT_OFF; float* whalt_s = dsm + WHALT_OFF;
    float* gx_sh = dsm + GX_OFF;

    __shared__ float gate_sh[512];
    __shared__ float acch_sh[128];
    __shared__ float x_sh[GB * 52];
    __shared__ float boutsh[OUTF];
    __shared__ float p_s[8];
    __shared__ int   alldone_sh;
    __shared__ float vb[16][68];
    __shared__ float msm[16][6], mss[16][6];

    // ---------------- prologue ----------------
    for (int f4 = tid; f4 < 64 * 128; f4 += NTHR) {
        int r = f4 >> 7, kk = (f4 & 127) << 2;
        int gr = (r >> 4) * HH + js * 16 + (r & 15);
        float4 wv = *reinterpret_cast<const float4*>(Whh + (size_t)gr * HH + kk);
        *reinterpret_cast<float4*>(whh_s + r * PAD + kk) = wv;
    }
    for (int i = tid; i < 64 * 51; i += NTHR) {
        int r = i / 51, k = i - r * 51;
        int gr = (r >> 4) * HH + js * 16 + (r & 15);
        wih_s[r * 52 + k] = Wih[(size_t)gr * 51 + k];
    }
    for (int i = tid; i < OUTF * 16; i += NTHR)
        wout_s[i] = Wout[(size_t)(i >> 4) * HH + js * 16 + (i & 15)];
    if (tid < 16)   whalt_s[tid] = Whalt[js * 16 + tid];
    if (tid < OUTF) boutsh[tid]  = bout[tid];
    {   // zero this CTA's share of yacc
        const int chunk = GB * TT * OUTF / NJS;
        float* base = g_yacc + (size_t)bgbase * TT * OUTF + (size_t)js * chunk;
        for (int i = tid; i < chunk; i += NTHR) __stcg(base + i, 0.0f);
    }
    int hb = 1;                                    // stage h0=0 into buffer 1
    #pragma unroll
    for (int i = 0; i < 8; i++) dsm[H_OFF + hb * 8 * PAD + i * PAD + tid] = 0.0f;
    for (int i = tid; i < GB * NIN; i += NTHR) {
        int bb = i / NIN, k = i - bb * NIN;
        x_sh[bb * 52 + k] = x[((size_t)(bgbase + bb) * TT) * NIN + k];
    }
    __syncthreads();

    const float brow = bias[grow];
    float flw0 = 0.f, flw1 = 0.f, flw2 = 0.f, flw3 = 0.f;
    if (tid < 128) {
        int jl = tid >> 3;
        flw0 = wih_s[jl * 52 + 50];        flw1 = wih_s[(16 + jl) * 52 + 50];
        flw2 = wih_s[(32 + jl) * 52 + 50]; flw3 = wih_s[(48 + jl) * 52 + 50];
    }
    {   float s0 = brow, s1 = 0.f;
        #pragma unroll
        for (int k = 0; k < 25; k++) s0 += x_sh[bl8 * 52 + k] * wih_s[rowl * 52 + k];
        #pragma unroll
        for (int k = 25; k < NIN; k++) s1 += x_sh[bl8 * 52 + k] * wih_s[rowl * 52 + k];
        gx_sh[rowl * 8 + bl8] = s0 + s1;
    }
    // pre-loop group barrier (slot value 1)
    __syncthreads();
    if (tid == 0) st_rel(&g_slot[bg][js][0], 1u);
    else if (tid >= 480) {
        while (ld_acq(&g_slot[bg][lane][0]) < 1u) __nanosleep(64);
    }
    __syncthreads();

    unsigned eflag = 0;
    float c_reg = 0.f, accc_reg = 0.f, acch_reg = 0.f, h2_reg = 0.f;
    float ha0=0.f,ha1=0.f,ha2=0.f,ha3=0.f,ha4=0.f,ha5=0.f,ha6=0.f,ha7=0.f;
    float cum_o = 0.f, pond_o = 0.f;
    int   done_o = 0;

    // ================= time loop =================
    for (int t = 0; t < TT; t++) {
        for (int it = 0; it <= MAXP; it++) {
            float4 sv0, sv1;
            if (it > 0) {
                const unsigned tgt = eflag;
                const int par = (int)(eflag & 1u);
                if (w == 15) {
                    // wait ALL 32 CTA flags (halt partials span the group)
                    for (;;) {
                        unsigned f = ld_acq(&g_flag[bg][lane][0]);
                        if (__all_sync(0xffffffffu, f >= tgt)) break;
                    }
                    asm volatile("fence.acq_rel.gpu;" ::: "memory");
                    // replicated ACT for step it-1 (lane owns b_own)
                    float hd = 0.f;
                    const float4* hp4 =
                        reinterpret_cast<const float4*>(&g_haltp[par][bg][0][0]);
                    #pragma unroll
                    for (int q = 0; q < 8; q++) {
                        float4 hv = __ldcg(&hp4[(jgrp + q * 4) * 8 + b_own]);
                        hd += (hv.x + hv.y) + (hv.z + hv.w);
                    }
                    hd += __shfl_xor_sync(0xffffffffu, hd, 8);
                    hd += __shfl_xor_sync(0xffffffffu, hd, 16);
                    float halt = sigm(hd + bhalt);
                    int wasdone = done_o;
                    int halted  = ((cum_o + halt) > 0.99f) || (it == MAXP);
                    float p_own = wasdone ? 0.f : (halted ? (1.f - cum_o) : halt);
                    pond_o += wasdone ? 0.f : 1.f;
                    if (!wasdone && halted) pond_o += 1.f - cum_o;
                    cum_o  += wasdone ? 0.f : halt;
                    done_o  = wasdone || halted;
                    int all = ((__ballot_sync(0xffffffffu, done_o) & 0xffu) == 0xffu);
                    if (lane < 8) p_s[lane] = p_own;
                    if (lane == 0) alldone_sh = all;
                } else {
                    // each lane acquires the flag of the CTA producing ITS data
                    const unsigned* fp = &g_flag[bg][w * 2 + (lane >> 4)][0];
                    for (;;) {
                        unsigned f = ld_acq(fp);
                        if (__all_sync(0xffffffffu, f >= tgt)) break;
                    }
                }
                // per-thread h loads (own CTA's data; acquire per-lane above)
                const float* hbp = &g_hstep[par][bg][0][0];
                sv0 = __ldcg(reinterpret_cast<const float4*>(hbp + tid * 8));
                sv1 = __ldcg(reinterpret_cast<const float4*>(hbp + tid * 8 + 4));
                hb ^= 1;
                float* hs = dsm + H_OFF + hb * 8 * PAD;
                hs[0*PAD+tid]=sv0.x; hs[1*PAD+tid]=sv0.y;
                hs[2*PAD+tid]=sv0.z; hs[3*PAD+tid]=sv0.w;
                hs[4*PAD+tid]=sv1.x; hs[5*PAD+tid]=sv1.y;
                hs[6*PAD+tid]=sv1.z; hs[7*PAD+tid]=sv1.w;
            }
            __syncthreads();                       // S1: the ONE full bar per step
            if (it > 0) {
                float p0=p_s[0],p1=p_s[1],p2=p_s[2],p3=p_s[3];
                float p4=p_s[4],p5=p_s[5],p6=p_s[6],p7=p_s[7];
                ha0+=p0*sv0.x; ha1+=p1*sv0.y; ha2+=p2*sv0.z; ha3+=p3*sv0.w;
                ha4+=p4*sv1.x; ha5+=p5*sv1.y; ha6+=p6*sv1.z; ha7+=p7*sv1.w;
                if (tid < 128) {
                    float pb = p_s[tid & 7];
                    accc_reg += pb * c_reg;
                    acch_reg += pb * h2_reg;
                }
                if (alldone_sh) break;
                if (it == MAXP) break;             // unreachable safety
            }
            eflag++;
            const int parp = (int)(eflag & 1u);
            // ---- GEMM (warps 0-7) ----
            if (tid < 256) {
                const int rp = tid >> 3, blg = tid & 7;
                const int r0 = rp * 2, r1 = r0 + 1;
                const float* hsrc = dsm + H_OFF + hb * 8 * PAD;
                const ulonglong2* __restrict__ w0 =
                    reinterpret_cast<const ulonglong2*>(whh_s + r0 * PAD);
                const ulonglong2* __restrict__ w1 =
                    reinterpret_cast<const ulonglong2*>(whh_s + r1 * PAD);
                const ulonglong2* __restrict__ hp =
                    reinterpret_cast<const ulonglong2*>(hsrc + blg * PAD);
                unsigned long long a00=0ull,a01=0ull,a10=0ull,a11=0ull;
                #pragma unroll 8
                for (int k = 0; k < 128; k++) {
                    ulonglong2 hv = hp[k], wa = w0[k], wb = w1[k];
                    ffma2(a00, wa.x, hv.x); ffma2(a01, wa.y, hv.y);
                    ffma2(a10, wb.x, hv.x); ffma2(a11, wb.y, hv.y);
                }
                float2 u0=unpk(a00),u1=unpk(a01),u2=unpk(a10),u3=unpk(a11);
                gate_sh[r0 * 8 + blg] = (u0.x+u0.y)+(u1.x+u1.y);
                gate_sh[r1 * 8 + blg] = (u2.x+u2.y)+(u3.x+u3.y);
                asm volatile("bar.sync 1, 256;" ::: "memory");
            }
            // ---- pointwise + publish (warps 0-3) ----
            if (tid < 128) {
                const int jl = tid >> 3, blp = tid & 7;
                const float fl = (it == 0) ? 1.0f : 0.0f;
                float gi = gate_sh[jl*8+blp]      + gx_sh[jl*8+blp]      + fl*flw0;
                float gf = gate_sh[(16+jl)*8+blp] + gx_sh[(16+jl)*8+blp] + fl*flw1;
                float gg = gate_sh[(32+jl)*8+blp] + gx_sh[(32+jl)*8+blp] + fl*flw2;
                float go = gate_sh[(48+jl)*8+blp] + gx_sh[(48+jl)*8+blp] + fl*flw3;
                float c2 = sigm(gf) * c_reg + sigm(gi) * tanhf(gg);
                float h2 = sigm(go) * tanhf(c2);
                c_reg = c2; h2_reg = h2;
                __stcg(&g_hstep[parp][bg][js * 16 + jl][blp], h2);
                float hwv = h2 * whalt_s[jl];
                hwv += __shfl_xor_sync(0xffffffffu, hwv, 8);
                hwv += __shfl_xor_sync(0xffffffffu, hwv, 16);
                if (lane < 8)
                    __stcg(&g_haltp[parp][bg][js][lane * 4 + w], hwv);
                asm volatile("bar.sync 2, 128;" ::: "memory");
                if (tid == 0) st_rel(&g_flag[bg][js][0], eflag);
            }
        }

        // ---------- timestep transition (no group barrier) ----------
        hb ^= 1;
        {   float* hs = dsm + H_OFF + hb * 8 * PAD;
            hs[0*PAD+tid]=ha0; hs[1*PAD+tid]=ha1; hs[2*PAD+tid]=ha2; hs[3*PAD+tid]=ha3;
            hs[4*PAD+tid]=ha4; hs[5*PAD+tid]=ha5; hs[6*PAD+tid]=ha6; hs[7*PAD+tid]=ha7;
        }
        ha0=ha1=ha2=ha3=ha4=ha5=ha6=ha7=0.f;
        if (tid < 128) {
            acch_sh[tid] = acch_reg;
            c_reg = accc_reg; accc_reg = 0.f; acch_reg = 0.f;
        }
        if (w == 15) {
            if (js == 0 && lane < 8)
                pout[(size_t)(bgbase + lane) * TT + t] = pond_o;
            cum_o = 0.f; pond_o = 0.f; done_o = 0;
        }
        if (t + 1 < TT && tid < GB * NIN) {
            int bb = tid / NIN, k = tid - bb * NIN;
            x_sh[bb * 52 + k] = x[((size_t)(bgbase + bb) * TT + (t + 1)) * NIN + k];
        }
        __syncthreads();                           // T-A
        {   // y projection once per timestep (linearity of W_out)
            int o = tid >> 3, blp = tid & 7;
            float s = 0.f;
            #pragma unroll
            for (int jl = 0; jl < 16; jl++) s += acch_sh[jl * 8 + blp] * wout_s[o * 16 + jl];
            atomicAdd(&g_yacc[((size_t)(bgbase + blp) * TT + t) * OUTF + o], s);
            if (tid < 16) {
                int idx = 512 + tid, o2 = idx >> 3, bl2 = idx & 7;
                float s2 = 0.f;
                #pragma unroll
                for (int jl = 0; jl < 16; jl++)
                    s2 += acch_sh[jl * 8 + bl2] * wout_s[o2 * 16 + jl];
                atomicAdd(&g_yacc[((size_t)(bgbase + bl2) * TT + t) * OUTF + o2], s2);
            }
        }
        if (t + 1 < TT) {
            float s0 = brow, s1 = 0.f;
            #pragma unroll
            for (int k = 0; k < 25; k++) s0 += x_sh[bl8 * 52 + k] * wih_s[rowl * 52 + k];
            #pragma unroll
            for (int k = 25; k < NIN; k++) s1 += x_sh[bl8 * 52 + k] * wih_s[rowl * 52 + k];
            gx_sh[rowl * 8 + bl8] = s0 + s1;       // read post next S1
        }
    }

    // ---------------- epilogue: group barrier (slot=2) + fused softmax ----------------
    __syncthreads();
    if (tid == 0) st_rel(&g_slot[bg][js][0], 2u);
    else if (tid >= 480) {
        while (ld_acq(&g_slot[bg][lane][0]) < 2u) __nanosleep(64);
    }
    __syncthreads();
    {
        for (int k = 0; k < 8; k++) {
            int q = js * 128 + w * 8 + k;
            int bloc = q >> 9, tt = q & 511;
            size_t base = ((size_t)(bgbase + bloc) * TT + tt) * OUTF;
            vb[w][lane]      = __ldcg(&g_yacc[base + lane])      + boutsh[lane];
            vb[w][32 + lane] = __ldcg(&g_yacc[base + 32 + lane]) + boutsh[32 + lane];
            if (lane < 2)
                vb[w][64 + lane] = __ldcg(&g_yacc[base + 64 + lane]) + boutsh[64 + lane];
            __syncwarp();
            if (lane < 6) {
                float m = -1e30f;
                #pragma unroll
                for (int q2 = 0; q2 < 11; q2++) m = fmaxf(m, vb[w][lane * 11 + q2]);
                float s = 0.f;
                #pragma unroll
                for (int q2 = 0; q2 < 11; q2++) s += expf(vb[w][lane * 11 + q2] - m);
                msm[w][lane] = m; mss[w][lane] = s;
            }
            __syncwarp();
            {
                int d0 = lane / 11, d1 = (32 + lane) / 11;
                out[base + lane]      = expf(vb[w][lane]      - msm[w][d0]) / mss[w][d0];
                out[base + 32 + lane] = expf(vb[w][32 + lane] - msm[w][d1]) / mss[w][d1];
                if (lane < 2)
                    out[base + 64 + lane] = expf(vb[w][64 + lane] - msm[w][5]) / mss[w][5];
            }
            __syncwarp();
        }
    }

    // ---------------- exit: reset flags for the next graph replay ----------------
    __syncthreads();
    if (tid == 0) {
        __threadfence();
        unsigned a = atomicAdd(&g_exitcnt[bg * 32], 1u);
        if (a == 31u) {
            atomicExch(&g_exitcnt[bg * 32], 0u);
            for (int q = 0; q < NJS; q++) {
                atomicExch(&g_slot[bg][q][0], 0u);
                atomicExch(&g_flag[bg][q][0], 0u);
            }
        }
    }
}

extern "C" void kernel_launch(void* const* d_in, const int* in_sizes, int n_in,
                              void* d_out, int out_size) {
    const float* x     = (const float*)d_in[0];
    const float* Wih   = (const float*)d_in[1];
    const float* Whh   = (const float*)d_in[2];
    const float* b     = (const float*)d_in[3];
    const float* Wout  = (const float*)d_in[4];
    const float* bout  = (const float*)d_in[5];
    const float* Whalt = (const float*)d_in[6];
    const float* bhalt = (const float*)d_in[7];
    float* out = (float*)d_out;

    cudaFuncSetAttribute(act_lstm_main, cudaFuncAttributeMaxDynamicSharedMemorySize,
                         DSM_FLOATS * 4);
    act_lstm_main<<<NCTA, NTHR, DSM_FLOATS * 4>>>(x, Wih, Whh, b, Wout, bout,
                                                  Whalt, bhalt, out);
}

// round 17
// speedup vs baseline: 1.0617x; 1.0617x over previous
#include <cuda_runtime.h>
#include <math.h>
#include <stdint.h>

#define NB    32
#define TT    512
#define NIN   50
#define HH    512
#define OUTF  66
#define MAXP  10
#define NJS   32
#define NBG   4
#define GB    8
#define NTHR  512
#define NCTA  128
#define PAD   516      // h rows: 516 mod 32 = 4
#define RPS   1036     // whh row-PAIR stride (floats): 48*rp mod 128 distinct banks
#define ROFF  520      // second row offset within pair: +32 bank phase, distinct

__device__ float    g_hstep[2][NBG][HH][GB];     // parity h2 exchange, [j][b]
__device__ float    g_haltp[2][NBG][NJS][32];    // halt partials: [js][b*4+w]
__device__ unsigned g_wflag[NBG][NJS][4][32];    // per-producer-warp epoch flags
__device__ float    g_yacc[NB * TT * OUTF];
__device__ unsigned g_slot[NBG][NJS][32];
__device__ unsigned g_exitcnt[NBG * 32];

__device__ __forceinline__ float sigm(float v) { return 1.0f / (1.0f + __expf(-v)); }
__device__ __forceinline__ void ffma2(unsigned long long& d, unsigned long long a,
                                      unsigned long long b) {
    asm("fma.rn.f32x2 %0, %1, %2, %0;" : "+l"(d) : "l"(a), "l"(b));
}
__device__ __forceinline__ float2 unpk(unsigned long long v) {
    float2 r; asm("mov.b64 {%0, %1}, %2;" : "=f"(r.x), "=f"(r.y) : "l"(v)); return r;
}
__device__ __forceinline__ unsigned ld_acq(const unsigned* p) {
    unsigned v;
    asm volatile("ld.acquire.gpu.global.u32 %0, [%1];" : "=r"(v) : "l"(p) : "memory");
    return v;
}
__device__ __forceinline__ void st_rel(unsigned* p, unsigned v) {
    asm volatile("st.release.gpu.global.u32 [%0], %1;" :: "l"(p), "r"(v) : "memory");
}

#define WHH_OFF    0                         // [32 pairs][RPS]
#define WIH_OFF    (32 * RPS)                // 33152  [64][52]
#define WOUT_OFF   (WIH_OFF + 64 * 52)       // [66][16]
#define WHALT_OFF  (WOUT_OFF + 66 * 16)      // [16]
#define H_OFF      (WHALT_OFF + 16)          // [8][PAD]
#define GX_OFF     (H_OFF + 8 * PAD)         // [512]
#define DSM_FLOATS (GX_OFF + 512)

extern __shared__ float dsm[];

__global__ void __launch_bounds__(NTHR, 1)
act_lstm_main(const float* __restrict__ x,   const float* __restrict__ Wih,
              const float* __restrict__ Whh, const float* __restrict__ bias,
              const float* __restrict__ Wout,const float* __restrict__ bout,
              const float* __restrict__ Whalt,const float* __restrict__ bhaltp,
              float* __restrict__ out)
{
    const int bg = blockIdx.x >> 5, js = blockIdx.x & 31, bgbase = bg * GB;
    const int tid = threadIdx.x, lane = tid & 31, w = tid >> 5;
    const int rowl = tid >> 3, bl8 = tid & 7;
    const int grow = (rowl >> 4) * HH + js * 16 + (rowl & 15);
    const int b_own = lane & 7, jgrp = lane >> 3;
    const float bhalt = bhaltp[0];
    float* pout = out + (size_t)NB * TT * OUTF;

    float* whh_s = dsm + WHH_OFF;  float* wih_s   = dsm + WIH_OFF;
    float* wout_s = dsm + WOUT_OFF; float* whalt_s = dsm + WHALT_OFF;
    float* h_sh = dsm + H_OFF;     float* gx_sh  = dsm + GX_OFF;

    __shared__ float gate_sh[512];
    __shared__ float acch_sh[128];
    __shared__ float x_sh[GB * 52];
    __shared__ float boutsh[OUTF];
    __shared__ float vb[16][68];
    __shared__ float msm[16][6], mss[16][6];

    // ---------------- prologue ----------------
    for (int f4 = tid; f4 < 64 * 128; f4 += NTHR) {
        int r = f4 >> 7, kk = (f4 & 127) << 2;
        int gr = (r >> 4) * HH + js * 16 + (r & 15);
        float4 wv = *reinterpret_cast<const float4*>(Whh + (size_t)gr * HH + kk);
        *reinterpret_cast<float4*>(whh_s + (r >> 1) * RPS + (r & 1) * ROFF + kk) = wv;
    }
    for (int i = tid; i < 64 * 51; i += NTHR) {
        int r = i / 51, k = i - r * 51;
        int gr = (r >> 4) * HH + js * 16 + (r & 15);
        wih_s[r * 52 + k] = Wih[(size_t)gr * 51 + k];
    }
    for (int i = tid; i < OUTF * 16; i += NTHR)
        wout_s[i] = Wout[(size_t)(i >> 4) * HH + js * 16 + (i & 15)];
    if (tid < 16)   whalt_s[tid] = Whalt[js * 16 + tid];
    if (tid < OUTF) boutsh[tid]  = bout[tid];
    {   // zero this CTA's share of yacc
        const int chunk = GB * TT * OUTF / NJS;
        float* base = g_yacc + (size_t)bgbase * TT * OUTF + (size_t)js * chunk;
        for (int i = tid; i < chunk; i += NTHR) __stcg(base + i, 0.0f);
    }
    #pragma unroll
    for (int i = 0; i < 8; i++) h_sh[i * PAD + tid] = 0.0f;
    for (int i = tid; i < GB * NIN; i += NTHR) {
        int bb = i / NIN, k = i - bb * NIN;
        x_sh[bb * 52 + k] = x[((size_t)(bgbase + bb) * TT) * NIN + k];
    }
    __syncthreads();

    const float brow = bias[grow];
    float flw0 = 0.f, flw1 = 0.f, flw2 = 0.f, flw3 = 0.f;
    if (tid < 128) {
        int jl = tid >> 3;
        flw0 = wih_s[jl * 52 + 50];        flw1 = wih_s[(16 + jl) * 52 + 50];
        flw2 = wih_s[(32 + jl) * 52 + 50]; flw3 = wih_s[(48 + jl) * 52 + 50];
    }
    {   float s0 = brow, s1 = 0.f;
        #pragma unroll
        for (int k = 0; k < 25; k++) s0 += x_sh[bl8 * 52 + k] * wih_s[rowl * 52 + k];
        #pragma unroll
        for (int k = 25; k < NIN; k++) s1 += x_sh[bl8 * 52 + k] * wih_s[rowl * 52 + k];
        gx_sh[rowl * 8 + bl8] = s0 + s1;
    }
    // pre-loop group barrier (slot value 1)
    __syncthreads();
    if (tid == 0) st_rel(&g_slot[bg][js][0], 1u);
    else if (tid >= 480) {
        while (ld_acq(&g_slot[bg][lane][0]) < 1u) __nanosleep(64);
    }
    __syncthreads();

    unsigned estep = 1;
    float c_reg = 0.f, accc_reg = 0.f, acch_reg = 0.f, h2_reg = 0.f;
    float ha0=0.f,ha1=0.f,ha2=0.f,ha3=0.f,ha4=0.f,ha5=0.f,ha6=0.f,ha7=0.f;
    float cum_o = 0.f, pond_o = 0.f;
    int   done_o = 0;

    // ================= time loop =================
    for (int t = 0; t < TT; t++) {
        for (int n = 0; n < MAXP; n++) {
            const int par = estep & 1;
            __syncthreads();                               // S1: h_sh staged
            if (tid < 128) {
                // ---- balanced GEMM: 2 rows x 2 batches per thread ----
                {
                    const int rp = tid >> 2, bp = tid & 3;
                    const ulonglong2* __restrict__ w0 =
                        reinterpret_cast<const ulonglong2*>(whh_s + rp * RPS);
                    const ulonglong2* __restrict__ w1 =
                        reinterpret_cast<const ulonglong2*>(whh_s + rp * RPS + ROFF);
                    const ulonglong2* __restrict__ h0 =
                        reinterpret_cast<const ulonglong2*>(h_sh + (2 * bp) * PAD);
                    const ulonglong2* __restrict__ h1 =
                        reinterpret_cast<const ulonglong2*>(h_sh + (2 * bp) * PAD + PAD);
                    unsigned long long a00=0ull,b00=0ull,a01=0ull,b01=0ull;
                    unsigned long long a10=0ull,b10=0ull,a11=0ull,b11=0ull;
                    #pragma unroll 8
                    for (int k = 0; k < 128; k++) {
                        ulonglong2 hv0 = h0[k], hv1 = h1[k];
                        ulonglong2 wa = w0[k],  wb = w1[k];
                        ffma2(a00, wa.x, hv0.x); ffma2(b00, wa.y, hv0.y);
                        ffma2(a01, wa.x, hv1.x); ffma2(b01, wa.y, hv1.y);
                        ffma2(a10, wb.x, hv0.x); ffma2(b10, wb.y, hv0.y);
                        ffma2(a11, wb.x, hv1.x); ffma2(b11, wb.y, hv1.y);
                    }
                    const int r0 = rp * 2, r1 = r0 + 1;
                    float2 u;
                    float g00, g01, g10, g11;
                    u = unpk(a00); g00  = u.x + u.y; u = unpk(b00); g00 += u.x + u.y;
                    u = unpk(a01); g01  = u.x + u.y; u = unpk(b01); g01 += u.x + u.y;
                    u = unpk(a10); g10  = u.x + u.y; u = unpk(b10); g10 += u.x + u.y;
                    u = unpk(a11); g11  = u.x + u.y; u = unpk(b11); g11 += u.x + u.y;
                    *reinterpret_cast<float2*>(gate_sh + r0 * 8 + 2 * bp) =
                        make_float2(g00, g01);
                    *reinterpret_cast<float2*>(gate_sh + r1 * 8 + 2 * bp) =
                        make_float2(g10, g11);
                }
                asm volatile("bar.sync 1, 128;" ::: "memory");   // gates ready (warps 0-3)
                // ---- pointwise + publish ----
                const int jl = tid >> 3, blp = tid & 7;
                const float fl = (n == 0) ? 1.0f : 0.0f;
                float gi = gate_sh[jl*8+blp]      + gx_sh[jl*8+blp]      + fl*flw0;
                float gf = gate_sh[(16+jl)*8+blp] + gx_sh[(16+jl)*8+blp] + fl*flw1;
                float gg = gate_sh[(32+jl)*8+blp] + gx_sh[(32+jl)*8+blp] + fl*flw2;
                float go = gate_sh[(48+jl)*8+blp] + gx_sh[(48+jl)*8+blp] + fl*flw3;
                float c2 = sigm(gf) * c_reg + sigm(gi) * tanhf(gg);
                float h2 = sigm(go) * tanhf(c2);
                c_reg = c2; h2_reg = h2;
                __stcg(&g_hstep[par][bg][js * 16 + jl][blp], h2);
                float hwv = h2 * whalt_s[jl];
                hwv += __shfl_xor_sync(0xffffffffu, hwv, 8);
                hwv += __shfl_xor_sync(0xffffffffu, hwv, 16);
                if (lane < 8)
                    __stcg(&g_haltp[par][bg][js][lane * 4 + w], hwv);
                __syncwarp();
                if (lane == 0) st_rel(&g_wflag[bg][js][w][0], estep);
            } else if (tid >= 384) {                       // pollers: 1 flag/thread
                const int q = tid - 384;
                while (ld_acq(&g_wflag[bg][q >> 2][q & 3][0]) < estep) __nanosleep(32);
            }
            __syncthreads();                               // S3: all 128 flags seen
            // ---- loads ----
            float4 v0, v1;
            {   const float* hb = &g_hstep[par][bg][0][0];
                v0 = __ldcg(reinterpret_cast<const float4*>(hb + tid * 8));
                v1 = __ldcg(reinterpret_cast<const float4*>(hb + tid * 8 + 4));
            }
            // ---- replicated-lite ACT: lane owns batch b_own ----
            float hd = 0.f;
            {   const float4* hp4 = reinterpret_cast<const float4*>(&g_haltp[par][bg][0][0]);
                #pragma unroll
                for (int q = 0; q < 8; q++) {
                    float4 hv = __ldcg(&hp4[(jgrp + q * 4) * 8 + b_own]);
                    hd += (hv.x + hv.y) + (hv.z + hv.w);
                }
                hd += __shfl_xor_sync(0xffffffffu, hd, 8);
                hd += __shfl_xor_sync(0xffffffffu, hd, 16);
            }
            float halt = sigm(hd + bhalt);
            int wasdone = done_o;
            int halted  = ((cum_o + halt) > 0.99f) || (n == MAXP - 1);
            float p_own = wasdone ? 0.f : (halted ? (1.f - cum_o) : halt);
            pond_o += wasdone ? 0.f : 1.f;
            if (!wasdone && halted) pond_o += 1.f - cum_o;
            cum_o  += wasdone ? 0.f : halt;
            done_o  = wasdone || halted;
            int alldone = ((__ballot_sync(0xffffffffu, done_o) & 0xffu) == 0xffu);
            float p0=__shfl_sync(0xffffffffu,p_own,0), p1=__shfl_sync(0xffffffffu,p_own,1);
            float p2=__shfl_sync(0xffffffffu,p_own,2), p3=__shfl_sync(0xffffffffu,p_own,3);
            float p4=__shfl_sync(0xffffffffu,p_own,4), p5=__shfl_sync(0xffffffffu,p_own,5);
            float p6=__shfl_sync(0xffffffffu,p_own,6), p7=__shfl_sync(0xffffffffu,p_own,7);
            // ---- weighted accumulation (registers) ----
            ha0 += p0*v0.x; ha1 += p1*v0.y; ha2 += p2*v0.z; ha3 += p3*v0.w;
            ha4 += p4*v1.x; ha5 += p5*v1.y; ha6 += p6*v1.z; ha7 += p7*v1.w;
            if (tid < 128) {          // blp == b_own for these threads
                accc_reg += p_own * c_reg;
                acch_reg += p_own * h2_reg;
            }
            estep++;
            if (alldone) break;
            h_sh[0*PAD+tid]=v0.x; h_sh[1*PAD+tid]=v0.y;
            h_sh[2*PAD+tid]=v0.z; h_sh[3*PAD+tid]=v0.w;
            h_sh[4*PAD+tid]=v1.x; h_sh[5*PAD+tid]=v1.y;
            h_sh[6*PAD+tid]=v1.z; h_sh[7*PAD+tid]=v1.w;
        }

        // ---------- timestep transition ----------
        h_sh[0*PAD+tid]=ha0; h_sh[1*PAD+tid]=ha1; h_sh[2*PAD+tid]=ha2; h_sh[3*PAD+tid]=ha3;
        h_sh[4*PAD+tid]=ha4; h_sh[5*PAD+tid]=ha5; h_sh[6*PAD+tid]=ha6; h_sh[7*PAD+tid]=ha7;
        ha0=ha1=ha2=ha3=ha4=ha5=ha6=ha7=0.f;
        if (tid < 128) {
            acch_sh[tid] = acch_reg;
            c_reg = accc_reg; accc_reg = 0.f; acch_reg = 0.f;
        }
        if (w == 15) {
            if (js == 0 && lane < 8)
                pout[(size_t)(bgbase + lane) * TT + t] = pond_o;
        }
        cum_o = 0.f; pond_o = 0.f; done_o = 0;
        if (t + 1 < TT && tid < GB * NIN) {
            int bb = tid / NIN, k = tid - bb * NIN;
            x_sh[bb * 52 + k] = x[((size_t)(bgbase + bb) * TT + (t + 1)) * NIN + k];
        }
        __syncthreads();                           // T-A
        {   // y projection once per timestep (linearity of W_out)
            int o = tid >> 3, blp = tid & 7;
            float s = 0.f;
            #pragma unroll
            for (int jl = 0; jl < 16; jl++) s += acch_sh[jl * 8 + blp] * wout_s[o * 16 + jl];
            atomicAdd(&g_yacc[((size_t)(bgbase + blp) * TT + t) * OUTF + o], s);
            if (tid < 16) {
                int idx = 512 + tid, o2 = idx >> 3, bl2 = idx & 7;
                float s2 = 0.f;
                #pragma unroll
                for (int jl = 0; jl < 16; jl++)
                    s2 += acch_sh[jl * 8 + bl2] * wout_s[o2 * 16 + jl];
                atomicAdd(&g_yacc[((size_t)(bgbase + bl2) * TT + t) * OUTF + o2], s2);
            }
        }
        if (t + 1 < TT) {
            float s0 = brow, s1 = 0.f;
            #pragma unroll
            for (int k = 0; k < 25; k++) s0 += x_sh[bl8 * 52 + k] * wih_s[rowl * 52 + k];
            #pragma unroll
            for (int k = 25; k < NIN; k++) s1 += x_sh[bl8 * 52 + k] * wih_s[rowl * 52 + k];
            gx_sh[rowl * 8 + bl8] = s0 + s1;       // consumed post next S1
        }
    }

    // ---------------- epilogue: group barrier (slot=2) + fused softmax ----------------
    __syncthreads();
    if (tid == 0) st_rel(&g_slot[bg][js][0], 2u);
    else if (tid >= 480) {
        while (ld_acq(&g_slot[bg][lane][0]) < 2u) __nanosleep(64);
    }
    __syncthreads();
    {
        for (int k = 0; k < 8; k++) {
            int q = js * 128 + w * 8 + k;
            int bloc = q >> 9, tt = q & 511;
            size_t base = ((size_t)(bgbase + bloc) * TT + tt) * OUTF;
            vb[w][lane]      = __ldcg(&g_yacc[base + lane])      + boutsh[lane];
            vb[w][32 + lane] = __ldcg(&g_yacc[base + 32 + lane]) + boutsh[32 + lane];
            if (lane < 2)
                vb[w][64 + lane] = __ldcg(&g_yacc[base + 64 + lane]) + boutsh[64 + lane];
            __syncwarp();
            if (lane < 6) {
                float m = -1e30f;
                #pragma unroll
                for (int q2 = 0; q2 < 11; q2++) m = fmaxf(m, vb[w][lane * 11 + q2]);
                float s = 0.f;
                #pragma unroll
                for (int q2 = 0; q2 < 11; q2++) s += expf(vb[w][lane * 11 + q2] - m);
                msm[w][lane] = m; mss[w][lane] = s;
            }
            __syncwarp();
            {
                int d0 = lane / 11, d1 = (32 + lane) / 11;
                out[base + lane]      = expf(vb[w][lane]      - msm[w][d0]) / mss[w][d0];
                out[base + 32 + lane] = expf(vb[w][32 + lane] - msm[w][d1]) / mss[w][d1];
                if (lane < 2)
                    out[base + 64 + lane] = expf(vb[w][64 + lane] - msm[w][5]) / mss[w][5];
            }
            __syncwarp();
        }
    }

    // ---------------- exit: reset flags for the next graph replay ----------------
    __syncthreads();
    if (tid == 0) {
        __threadfence();
        unsigned a = atomicAdd(&g_exitcnt[bg * 32], 1u);
        if (a == 31u) {
            atomicExch(&g_exitcnt[bg * 32], 0u);
            for (int q = 0; q < NJS; q++) {
                atomicExch(&g_slot[bg][q][0], 0u);
                for (int w2 = 0; w2 < 4; w2++) atomicExch(&g_wflag[bg][q][w2][0], 0u);
            }
        }
    }
}

extern "C" void kernel_launch(void* const* d_in, const int* in_sizes, int n_in,
                              void* d_out, int out_size) {
    const float* x     = (const float*)d_in[0];
    const float* Wih   = (const float*)d_in[1];
    const float* Whh   = (const float*)d_in[2];
    const float* b     = (const float*)d_in[3];
    const float* Wout  = (const float*)d_in[4];
    const float* bout  = (const float*)d_in[5];
    const float* Whalt = (const float*)d_in[6];
    const float* bhalt = (const float*)d_in[7];
    float* out = (float*)d_out;

    cudaFuncSetAttribute(act_lstm_main, cudaFuncAttributeMaxDynamicSharedMemorySize,
                         DSM_FLOATS * 4);
    act_lstm_main<<<NCTA, NTHR, DSM_FLOATS * 4>>>(x, Wih, Whh, b, Wout, bout,
                                                  Whalt, bhalt, out);
}